// round 15
// baseline (speedup 1.0000x reference)
#include <cuda_runtime.h>
#include <cuda_bf16.h>
#include <cstdint>

#define N_NODES 100000
#define E_EDGES 1600000
#define HID     64
#define IN_C    128
#define OUT_F   25
#define NCHUNK  98   // ceil(N/1024)
#define XP      72   // smem pitch (bf16) -> 144B row stride: conflict-free ldmatrix
#define HALF0   50048                 // multiple of 64
#define HALF1   (N_NODES - HALF0)     // 49952

// ---------------- device scratch (static: no allocations allowed) ----------
struct Scratch {
    int   count[N_NODES];                 // degree counts, later scatter cursor
    unsigned long long state[NCHUNK];     // decoupled-lookback scan state
    float pool[HID];                      // pooled accumulator
    unsigned int done;                    // pool last-block counter
};
__device__ Scratch g_s;
__device__ float g_dinv [N_NODES];      // rsqrt(deg+1)
__device__ int   g_off  [N_NODES + 1];  // CSR offsets (by col)
__device__ __align__(16) int g_src [E_EDGES];  // row indices sorted by col (16B aligned)
__device__ float g_h    [N_NODES * HID / 2]; // Hs bf16 buffer A
__device__ float g_x    [N_NODES * HID / 2]; // activations bf16 buffer
__device__ float g_y    [N_NODES * HID / 2]; // Hs bf16 buffer B (breaks WAR in pipeline)
// precomputed hi/lo bf16 weight splits
__device__ __nv_bfloat16 g_W1h[IN_C * HID], g_W1l[IN_C * HID];
__device__ __nv_bfloat16 g_W2h[HID * HID],  g_W2l[HID * HID];
__device__ __nv_bfloat16 g_W3h[HID * HID],  g_W3l[HID * HID];

#define FLAG_AGG  (1ull << 62)
#define FLAG_PREF (2ull << 62)

// ---------------- CSR build --------------------------------------------------
__global__ void count_kernel(const int4* __restrict__ col4) {
    int i = blockIdx.x * 256 + threadIdx.x;
    if (i < E_EDGES / 4) {
        int4 c = col4[i];
        atomicAdd(&g_s.count[c.x], 1);
        atomicAdd(&g_s.count[c.y], 1);
        atomicAdd(&g_s.count[c.z], 1);
        atomicAdd(&g_s.count[c.w], 1);
    }
}

// single-pass exclusive scan (decoupled lookback) + dinv + cursor reset
__global__ void __launch_bounds__(256)
scan_fused_kernel() {
    __shared__ int sh[256];
    __shared__ int s_prefix;
    int b = blockIdx.x, t = threadIdx.x;
    int base = b * 1024 + t * 4;
    int v0 = (base + 0 < N_NODES) ? g_s.count[base + 0] : 0;
    int v1 = (base + 1 < N_NODES) ? g_s.count[base + 1] : 0;
    int v2 = (base + 2 < N_NODES) ? g_s.count[base + 2] : 0;
    int v3 = (base + 3 < N_NODES) ? g_s.count[base + 3] : 0;
    int tot = v0 + v1 + v2 + v3;
    sh[t] = tot;
    __syncthreads();
    for (int o = 1; o < 256; o <<= 1) {
        int x = (t >= o) ? sh[t - o] : 0;
        __syncthreads();
        sh[t] += x;
        __syncthreads();
    }
    int btot = sh[255];

    if (t == 0) {
        if (b == 0) {
            s_prefix = 0;
            atomicExch(&g_s.state[0], FLAG_PREF | (unsigned long long)(unsigned)btot);
        } else {
            atomicExch(&g_s.state[b], FLAG_AGG | (unsigned long long)(unsigned)btot);
        }
    }
    if (b > 0 && t < 32) {
        int excl = 0;
        int hi = b - 1;
        for (;;) {
            int idx = hi - 31 + t;
            unsigned long long s;
            unsigned flag;
            for (;;) {
                s = (idx >= 0)
                    ? *((volatile unsigned long long*)&g_s.state[idx])
                    : FLAG_PREF;
                flag = (unsigned)(s >> 62);
                if (__all_sync(0xffffffffu, flag != 0)) break;
            }
            unsigned pm = __ballot_sync(0xffffffffu, flag == 2u);
            int val = (int)(s & 0xffffffffull);
            if (pm) {
                int lp = 31 - __clz(pm);
                int contrib = (t >= lp) ? val : 0;
#pragma unroll
                for (int o = 16; o > 0; o >>= 1)
                    contrib += __shfl_xor_sync(0xffffffffu, contrib, o);
                excl += contrib;
                break;
            } else {
                int contrib = val;
#pragma unroll
                for (int o = 16; o > 0; o >>= 1)
                    contrib += __shfl_xor_sync(0xffffffffu, contrib, o);
                excl += contrib;
                hi -= 32;
            }
        }
        if (t == 0) {
            s_prefix = excl;
            atomicExch(&g_s.state[b],
                       FLAG_PREF | (unsigned long long)(unsigned)(excl + btot));
        }
    }
    __syncthreads();
    int pref = s_prefix;
    int excl = pref + sh[t] - tot;
    if (base + 0 < N_NODES) {
        g_off[base + 0] = excl;
        g_dinv[base + 0] = rsqrtf((float)v0 + 1.0f);
        g_s.count[base + 0] = 0;
    }
    if (base + 1 < N_NODES) {
        g_off[base + 1] = excl + v0;
        g_dinv[base + 1] = rsqrtf((float)v1 + 1.0f);
        g_s.count[base + 1] = 0;
    }
    if (base + 2 < N_NODES) {
        g_off[base + 2] = excl + v0 + v1;
        g_dinv[base + 2] = rsqrtf((float)v2 + 1.0f);
        g_s.count[base + 2] = 0;
    }
    if (base + 3 < N_NODES) {
        g_off[base + 3] = excl + v0 + v1 + v2;
        g_dinv[base + 3] = rsqrtf((float)v3 + 1.0f);
        g_s.count[base + 3] = 0;
    }
    if (b == NCHUNK - 1 && t == 255) g_off[N_NODES] = pref + btot;
}

__global__ void scatter_kernel(const int4* __restrict__ row4, const int4* __restrict__ col4) {
    int i = blockIdx.x * 256 + threadIdx.x;
    if (i < E_EDGES / 4) {
        int4 r = row4[i];
        int4 c = col4[i];
        g_src[g_off[c.x] + atomicAdd(&g_s.count[c.x], 1)] = r.x;
        g_src[g_off[c.y] + atomicAdd(&g_s.count[c.y], 1)] = r.y;
        g_src[g_off[c.z] + atomicAdd(&g_s.count[c.z], 1)] = r.z;
        g_src[g_off[c.w] + atomicAdd(&g_s.count[c.w], 1)] = r.w;
    }
}

// ---------------- weight prep: fp32 -> hi/lo bf16 (once, on side stream) ----
__global__ void wprep_kernel(const float* __restrict__ W1,
                             const float* __restrict__ W2,
                             const float* __restrict__ W3) {
    int i = blockIdx.x * 256 + threadIdx.x;
    float w;
    __nv_bfloat16 *ph, *pl;
    int j;
    if (i < IN_C * HID)                { j = i;                      w = W1[j]; ph = g_W1h; pl = g_W1l; }
    else if (i < IN_C * HID + HID*HID) { j = i - IN_C * HID;         w = W2[j]; ph = g_W2h; pl = g_W2l; }
    else if (i < IN_C*HID + 2*HID*HID) { j = i - IN_C*HID - HID*HID; w = W3[j]; ph = g_W3h; pl = g_W3l; }
    else return;
    __nv_bfloat16 h = __float2bfloat16(w);
    ph[j] = h;
    pl[j] = __float2bfloat16(w - __bfloat162float(h));
}

// ---------------- tensor-core MMA helpers -----------------------------------
__device__ __forceinline__ void ldsm_x4(uint32_t& a0, uint32_t& a1, uint32_t& a2,
                                        uint32_t& a3, uint32_t addr) {
    asm volatile("ldmatrix.sync.aligned.m8n8.x4.shared.b16 {%0,%1,%2,%3}, [%4];"
                 : "=r"(a0), "=r"(a1), "=r"(a2), "=r"(a3) : "r"(addr));
}
__device__ __forceinline__ void ldsm_x2t(uint32_t& b0, uint32_t& b1, uint32_t addr) {
    asm volatile("ldmatrix.sync.aligned.m8n8.x2.trans.shared.b16 {%0,%1}, [%2];"
                 : "=r"(b0), "=r"(b1) : "r"(addr));
}
__device__ __forceinline__ void mma_bf16(float* c, uint32_t a0, uint32_t a1,
                                         uint32_t a2, uint32_t a3,
                                         uint32_t b0, uint32_t b1) {
    asm volatile(
        "mma.sync.aligned.m16n8k16.row.col.f32.bf16.bf16.f32 "
        "{%0,%1,%2,%3},{%4,%5,%6,%7},{%8,%9},{%0,%1,%2,%3};"
        : "+f"(c[0]), "+f"(c[1]), "+f"(c[2]), "+f"(c[3])
        : "r"(a0), "r"(a1), "r"(a2), "r"(a3), "r"(b0), "r"(b1));
}

// ---------------- tensor-core GEMM ------------------------------------------
template <int K, bool SCALE, bool F32SRC>
__global__ void __launch_bounds__(128)
gemm_kernel(const void* __restrict__ Xv,
            const __nv_bfloat16* __restrict__ Wh_g,
            const __nv_bfloat16* __restrict__ Wl_g,
            __nv_bfloat162* __restrict__ Hs, int m_base) {
    __shared__ __align__(16) __nv_bfloat16 Xs[64][XP];
    __shared__ __align__(16) __nv_bfloat16 Wh[64][XP];
    __shared__ __align__(16) __nv_bfloat16 Wl[64][XP];

    int tid  = threadIdx.x;
    int wp   = tid >> 5;
    int lane = tid & 31;
    int m0   = m_base + blockIdx.x * 64;

    float c[8][4];
#pragma unroll
    for (int a = 0; a < 8; a++)
#pragma unroll
        for (int b = 0; b < 4; b++) c[a][b] = 0.f;

    uint32_t xs_b = (uint32_t)__cvta_generic_to_shared(&Xs[0][0]);
    uint32_t wh_b = (uint32_t)__cvta_generic_to_shared(&Wh[0][0]);
    uint32_t wl_b = (uint32_t)__cvta_generic_to_shared(&Wl[0][0]);

    for (int kc = 0; kc < K; kc += 64) {
        for (int i = tid; i < 64 * 8; i += 128) {
            int k = i >> 3, q = i & 7;
            *reinterpret_cast<uint4*>(&Wh[k][q * 8]) =
                *reinterpret_cast<const uint4*>(&Wh_g[(kc + k) * HID + q * 8]);
            *reinterpret_cast<uint4*>(&Wl[k][q * 8]) =
                *reinterpret_cast<const uint4*>(&Wl_g[(kc + k) * HID + q * 8]);
        }
        if (F32SRC) {
            const float* X = (const float*)Xv;
#pragma unroll
            for (int l = 0; l < 8; l++) {
                int idx = l * 128 + tid;
                int row = idx >> 4;
                int q   = idx & 15;
                int m   = m0 + row;
                float4 v = make_float4(0.f, 0.f, 0.f, 0.f);
                if (m < N_NODES)
                    v = *reinterpret_cast<const float4*>(&X[(size_t)m * K + kc + q * 4]);
                *reinterpret_cast<__nv_bfloat162*>(&Xs[row][q * 4]) =
                    __float22bfloat162_rn(make_float2(v.x, v.y));
                *reinterpret_cast<__nv_bfloat162*>(&Xs[row][q * 4 + 2]) =
                    __float22bfloat162_rn(make_float2(v.z, v.w));
            }
        } else {
            const __nv_bfloat16* X = (const __nv_bfloat16*)Xv;
#pragma unroll
            for (int l = 0; l < 4; l++) {
                int idx = l * 128 + tid;
                int row = idx >> 3;
                int q   = idx & 7;
                int m   = m0 + row;
                uint4 v = make_uint4(0u, 0u, 0u, 0u);
                if (m < N_NODES)
                    v = *reinterpret_cast<const uint4*>(&X[(size_t)m * K + kc + q * 8]);
                *reinterpret_cast<uint4*>(&Xs[row][q * 8]) = v;
            }
        }
        __syncthreads();

#pragma unroll
        for (int ks = 0; ks < 4; ks++) {
            uint32_t a0, a1, a2, a3;
            int ar = wp * 16 + (lane & 15);
            int ak = ks * 16 + (lane >> 4) * 8;
            ldsm_x4(a0, a1, a2, a3, xs_b + (ar * XP + ak) * 2);
            int kg = ks * 16 + (lane & 15);
#pragma unroll
            for (int nt = 0; nt < 8; nt++) {
                uint32_t b0, b1;
                ldsm_x2t(b0, b1, wh_b + (kg * XP + nt * 8) * 2);
                mma_bf16(c[nt], a0, a1, a2, a3, b0, b1);
                ldsm_x2t(b0, b1, wl_b + (kg * XP + nt * 8) * 2);
                mma_bf16(c[nt], a0, a1, a2, a3, b0, b1);
            }
        }
        __syncthreads();
    }

    int gid = lane >> 2, tig = lane & 3;
    int r0 = m0 + wp * 16 + gid;
    int r1 = r0 + 8;
    if (r0 < N_NODES) {
        float dv = SCALE ? g_dinv[r0] : 1.0f;
#pragma unroll
        for (int nt = 0; nt < 8; nt++)
            Hs[(size_t)r0 * 32 + nt * 4 + tig] =
                __float22bfloat162_rn(make_float2(c[nt][0] * dv, c[nt][1] * dv));
    }
    if (r1 < N_NODES) {
        float dv = SCALE ? g_dinv[r1] : 1.0f;
#pragma unroll
        for (int nt = 0; nt < 8; nt++)
            Hs[(size_t)r1 * 32 + nt * 4 + tig] =
                __float22bfloat162_rn(make_float2(c[nt][2] * dv, c[nt][3] * dv));
    }
}

// multiply bf16 rows by dinv[v] (applied after gemm1, which runs before dinv exists)
__global__ void __launch_bounds__(256)
scale_kernel(__nv_bfloat162* __restrict__ Hs) {
    int idx = blockIdx.x * 256 + threadIdx.x;
    int v = idx >> 5;
    if (v >= N_NODES) return;
    float dv = g_dinv[v];
    float2 f = __bfloat1622float2(Hs[idx]);
    Hs[idx] = __float22bfloat162_rn(make_float2(f.x * dv, f.y * dv));
}

// ------- agg core: CSR gather + self-loop + bias + LN + ReLU ----------------
// index stream loaded as aligned int4 (1 LDG.128 = 4 indices vs 4 LDG.32);
// row-gather keeps 8 loads in flight.
__device__ __forceinline__ void agg_node(
    int v, int lane, const __nv_bfloat162* __restrict__ H2,
    const float* __restrict__ bias, const float* __restrict__ lnw,
    const float* __restrict__ lnb, float& y0o, float& y1o) {
    int beg = g_off[v], end = g_off[v + 1];

    float ax = 0.f, ay = 0.f;
    int e = beg;
    // peel to 16B alignment of &g_src[e]
    int lim = (beg + 3) & ~3;
    if (lim > end) lim = end;
    for (; e < lim; e++) {
        int s = g_src[e];
        float2 h = __bfloat1622float2(H2[(size_t)s * 32 + lane]);
        ax += h.x; ay += h.y;
    }
    // main loop: 8 edges = 2 aligned int4 index loads + 8 row gathers
    for (; e + 8 <= end; e += 8) {
        int4 sa = *reinterpret_cast<const int4*>(&g_src[e]);
        int4 sb = *reinterpret_cast<const int4*>(&g_src[e + 4]);
        float2 h0 = __bfloat1622float2(H2[(size_t)sa.x * 32 + lane]);
        float2 h1 = __bfloat1622float2(H2[(size_t)sa.y * 32 + lane]);
        float2 h2 = __bfloat1622float2(H2[(size_t)sa.z * 32 + lane]);
        float2 h3 = __bfloat1622float2(H2[(size_t)sa.w * 32 + lane]);
        float2 h4 = __bfloat1622float2(H2[(size_t)sb.x * 32 + lane]);
        float2 h5 = __bfloat1622float2(H2[(size_t)sb.y * 32 + lane]);
        float2 h6 = __bfloat1622float2(H2[(size_t)sb.z * 32 + lane]);
        float2 h7 = __bfloat1622float2(H2[(size_t)sb.w * 32 + lane]);
        ax += ((h0.x + h1.x) + (h2.x + h3.x)) + ((h4.x + h5.x) + (h6.x + h7.x));
        ay += ((h0.y + h1.y) + (h2.y + h3.y)) + ((h4.y + h5.y) + (h6.y + h7.y));
    }
    // 4-wide aligned chunk
    if (e + 4 <= end) {
        int4 sa = *reinterpret_cast<const int4*>(&g_src[e]);
        float2 h0 = __bfloat1622float2(H2[(size_t)sa.x * 32 + lane]);
        float2 h1 = __bfloat1622float2(H2[(size_t)sa.y * 32 + lane]);
        float2 h2 = __bfloat1622float2(H2[(size_t)sa.z * 32 + lane]);
        float2 h3 = __bfloat1622float2(H2[(size_t)sa.w * 32 + lane]);
        ax += (h0.x + h1.x) + (h2.x + h3.x);
        ay += (h0.y + h1.y) + (h2.y + h3.y);
        e += 4;
    }
    for (; e < end; e++) {
        int s = g_src[e];
        float2 h = __bfloat1622float2(H2[(size_t)s * 32 + lane]);
        ax += h.x; ay += h.y;
    }

    float dv = g_dinv[v];
    float2 hs = __bfloat1622float2(H2[(size_t)v * 32 + lane]);
    ax = (ax + hs.x) * dv + bias[lane * 2 + 0];
    ay = (ay + hs.y) * dv + bias[lane * 2 + 1];

    float sum = ax + ay;
    float sq  = ax * ax + ay * ay;
#pragma unroll
    for (int o = 16; o > 0; o >>= 1) {
        sum += __shfl_xor_sync(0xffffffffu, sum, o);
        sq  += __shfl_xor_sync(0xffffffffu, sq,  o);
    }
    float mu  = sum * (1.f / 64.f);
    float var = sq * (1.f / 64.f) - mu * mu;
    float r   = rsqrtf(var + 1e-5f);
    float t0 = (ax - mu) * r * lnw[lane * 2 + 0] + lnb[lane * 2 + 0];
    float t1 = (ay - mu) * r * lnw[lane * 2 + 1] + lnb[lane * 2 + 1];
    y0o = fmaxf(t0, 0.f);
    y1o = fmaxf(t1, 0.f);
}

// writes bf16 activations (consumed by tensor-core gemm2/3); node range version
__global__ void __launch_bounds__(256)
agg_ln_kernel(const __nv_bfloat162* __restrict__ H2, const float* __restrict__ bias,
              const float* __restrict__ lnw, const float* __restrict__ lnb,
              __nv_bfloat162* __restrict__ Xo, int v_base, int v_count) {
    int vl = (blockIdx.x * 256 + threadIdx.x) >> 5;
    int lane = threadIdx.x & 31;
    if (vl >= v_count) return;
    int v = v_base + vl;
    float y0, y1;
    agg_node(v, lane, H2, bias, lnw, lnb, y0, y1);
    Xo[(size_t)v * 32 + lane] = __float22bfloat162_rn(make_float2(y0, y1));
}

// layer 3: agg + LN + ReLU + mean-pool + (last block) final linear head
#define POOL_BLOCKS 1184
__global__ void __launch_bounds__(256)
agg_ln_pool_kernel(const __nv_bfloat162* __restrict__ H2, const float* __restrict__ bias,
                   const float* __restrict__ lnw, const float* __restrict__ lnb,
                   const float* __restrict__ Wl, const float* __restrict__ bl,
                   float* __restrict__ out) {
    __shared__ float shp[8 * 64];
    __shared__ int s_last;
    int w    = threadIdx.x >> 5;
    int lane = threadIdx.x & 31;
    int gw   = blockIdx.x * 8 + w;
    const int nw = POOL_BLOCKS * 8;

    float px = 0.f, py = 0.f;
    for (int v = gw; v < N_NODES; v += nw) {
        float y0, y1;
        agg_node(v, lane, H2, bias, lnw, lnb, y0, y1);
        px += y0; py += y1;
    }
    shp[w * 64 + lane * 2 + 0] = px;
    shp[w * 64 + lane * 2 + 1] = py;
    __syncthreads();
    if (threadIdx.x < 64) {
        float s = 0.f;
#pragma unroll
        for (int k = 0; k < 8; k++) s += shp[k * 64 + threadIdx.x];
        atomicAdd(&g_s.pool[threadIdx.x], s);
    }
    __syncthreads();
    if (threadIdx.x == 0) {
        __threadfence();
        unsigned t = atomicAdd(&g_s.done, 1u);
        s_last = (t == POOL_BLOCKS - 1) ? 1 : 0;
    }
    __syncthreads();
    if (s_last) {
        __threadfence();
        int o = threadIdx.x;
        if (o < OUT_F) {
            float s = 0.f;
#pragma unroll
            for (int j = 0; j < HID; j++) s += g_s.pool[j] * Wl[j * OUT_F + o];
            out[o] = s * (1.0f / N_NODES) + bl[o];
        }
    }
}

// ---------------- launch ----------------------------------------------------
extern "C" void kernel_launch(void* const* d_in, const int* in_sizes, int n_in,
                              void* d_out, int out_size) {
    const float* x    = (const float*)d_in[0];
    const int*   ei   = (const int*)  d_in[1];
    const float* W1   = (const float*)d_in[2];
    const float* b1   = (const float*)d_in[3];
    const float* W2   = (const float*)d_in[4];
    const float* b2   = (const float*)d_in[5];
    const float* W3   = (const float*)d_in[6];
    const float* b3   = (const float*)d_in[7];
    const float* ln1w = (const float*)d_in[8];
    const float* ln1b = (const float*)d_in[9];
    const float* ln2w = (const float*)d_in[10];
    const float* ln2b = (const float*)d_in[11];
    const float* ln3w = (const float*)d_in[12];
    const float* ln3b = (const float*)d_in[13];
    const float* Wl   = (const float*)d_in[14];
    const float* bl   = (const float*)d_in[15];
    float* out = (float*)d_out;

    const int4* row4 = (const int4*)(ei);             // edge_index[0]
    const int4* col4 = (const int4*)(ei + E_EDGES);   // edge_index[1]

    __nv_bfloat162* gh = nullptr; cudaGetSymbolAddress((void**)&gh, g_h);
    __nv_bfloat162* gx = nullptr; cudaGetSymbolAddress((void**)&gx, g_x);
    __nv_bfloat162* gy = nullptr; cudaGetSymbolAddress((void**)&gy, g_y);
    void*           gs = nullptr; cudaGetSymbolAddress(&gs, g_s);
    __nv_bfloat16 *w1h = nullptr, *w1l = nullptr, *w2h = nullptr, *w2l = nullptr,
                  *w3h = nullptr, *w3l = nullptr;
    cudaGetSymbolAddress((void**)&w1h, g_W1h);
    cudaGetSymbolAddress((void**)&w1l, g_W1l);
    cudaGetSymbolAddress((void**)&w2h, g_W2h);
    cudaGetSymbolAddress((void**)&w2l, g_W2l);
    cudaGetSymbolAddress((void**)&w3h, g_W3h);
    cudaGetSymbolAddress((void**)&w3l, g_W3l);

    int eB4  = (E_EDGES / 4 + 255) / 256;    // 1563
    int gB   = (N_NODES + 63) / 64;          // 1563 (gemm1: full range)
    int gB0  = HALF0 / 64;                   // 782
    int gB1h = (HALF1 + 63) / 64;            // 781
    int aB   = (N_NODES * 32 + 255) / 256;   // full-range (scale)
    int aB0  = (HALF0 * 32 + 255) / 256;
    int aB1  = (HALF1 * 32 + 255) / 256;

    cudaStream_t s, s2;
    cudaStreamCreateWithFlags(&s,  cudaStreamNonBlocking);
    cudaStreamCreateWithFlags(&s2, cudaStreamNonBlocking);
    cudaEvent_t eFork, eDinv, eScat, eJoin, eM1, eS1, eM2, eS2;
    cudaEventCreateWithFlags(&eFork, cudaEventDisableTiming);
    cudaEventCreateWithFlags(&eDinv, cudaEventDisableTiming);
    cudaEventCreateWithFlags(&eScat, cudaEventDisableTiming);
    cudaEventCreateWithFlags(&eJoin, cudaEventDisableTiming);
    cudaEventCreateWithFlags(&eM1, cudaEventDisableTiming);
    cudaEventCreateWithFlags(&eS1, cudaEventDisableTiming);
    cudaEventCreateWithFlags(&eM2, cudaEventDisableTiming);
    cudaEventCreateWithFlags(&eS2, cudaEventDisableTiming);

    // ---- main stream: CSR build ----
    cudaMemsetAsync(gs, 0, sizeof(Scratch), 0);   // count + scan state + pool + done
    cudaEventRecord(eFork, 0);
    count_kernel<<<eB4, 256>>>(col4);
    scan_fused_kernel<<<NCHUNK, 256>>>();
    cudaEventRecord(eDinv, 0);
    scatter_kernel<<<eB4, 256>>>(row4, col4);
    cudaEventRecord(eScat, 0);

    // ---- side stream: wprep -> gemm1 (no dinv) -> (wait dinv) -> scale ----
    cudaStreamWaitEvent(s, eFork, 0);
    wprep_kernel<<<64, 256, 0, s>>>(W1, W2, W3);
    gemm_kernel<IN_C, false, true><<<gB, 128, 0, s>>>(x, w1h, w1l, gh, 0);
    cudaStreamWaitEvent(s, eDinv, 0);
    scale_kernel<<<aB, 256, 0, s>>>(gh);
    cudaEventRecord(eJoin, s);

    // ---- pipelined layer transitions: half0 on stream 0, half1 on s2 ----
    cudaStreamWaitEvent(0, eJoin, 0);
    cudaStreamWaitEvent(s2, eJoin, 0);
    cudaStreamWaitEvent(s2, eScat, 0);

    // L1 agg(read gh) -> gemm2(write gy) per half
    agg_ln_kernel<<<aB0, 256>>>(gh, b1, ln1w, ln1b, gx, 0, HALF0);
    gemm_kernel<HID, true, false><<<gB0, 128>>>(gx, w2h, w2l, gy, 0);
    cudaEventRecord(eM1, 0);
    agg_ln_kernel<<<aB1, 256, 0, s2>>>(gh, b1, ln1w, ln1b, gx, HALF0, HALF1);
    gemm_kernel<HID, true, false><<<gB1h, 128, 0, s2>>>(gx, w2h, w2l, gy, HALF0);
    cudaEventRecord(eS1, s2);

    cudaStreamWaitEvent(0, eS1, 0);
    cudaStreamWaitEvent(s2, eM1, 0);

    // L2 agg(read gy) -> gemm3(write gh) per half
    agg_ln_kernel<<<aB0, 256>>>(gy, b2, ln2w, ln2b, gx, 0, HALF0);
    gemm_kernel<HID, true, false><<<gB0, 128>>>(gx, w3h, w3l, gh, 0);
    cudaEventRecord(eM2, 0);
    agg_ln_kernel<<<aB1, 256, 0, s2>>>(gy, b2, ln2w, ln2b, gx, HALF0, HALF1);
    gemm_kernel<HID, true, false><<<gB1h, 128, 0, s2>>>(gx, w3h, w3l, gh, HALF0);
    cudaEventRecord(eS2, s2);

    // L3: pool (+ fused final head) needs both halves of gemm3 output (gh)
    cudaStreamWaitEvent(0, eS2, 0);
    cudaStreamWaitEvent(0, eM2, 0);
    agg_ln_pool_kernel<<<POOL_BLOCKS, 256>>>(gh, b3, ln3w, ln3b, Wl, bl, out);

    cudaStreamDestroy(s);
    cudaStreamDestroy(s2);
    cudaEventDestroy(eFork);
    cudaEventDestroy(eDinv);
    cudaEventDestroy(eScat);
    cudaEventDestroy(eJoin);
    cudaEventDestroy(eM1);
    cudaEventDestroy(eS1);
    cudaEventDestroy(eM2);
    cudaEventDestroy(eS2);
}

// round 16
// speedup vs baseline: 1.0402x; 1.0402x over previous
#include <cuda_runtime.h>
#include <cuda_bf16.h>
#include <cstdint>

#define N_NODES 100000
#define E_EDGES 1600000
#define E_PAD   (E_EDGES + 3 * N_NODES + 16)   // CSR padded to 4-multiples per node
#define HID     64
#define IN_C    128
#define OUT_F   25
#define NCHUNK  98   // ceil(N/1024)
#define XP      72   // smem pitch (bf16) -> 144B row stride: conflict-free ldmatrix
#define HALF0   50048                 // multiple of 64
#define HALF1   (N_NODES - HALF0)     // 49952

// ---------------- device scratch (static: no allocations allowed) ----------
struct Scratch {
    int   count[N_NODES];                 // degree counts, later scatter cursor
    unsigned long long state[NCHUNK];     // decoupled-lookback scan state
    float pool[HID];                      // pooled accumulator
    unsigned int done;                    // pool last-block counter
};
__device__ Scratch g_s;
__device__ float g_dinv [N_NODES];      // rsqrt(deg+1)  (REAL degree)
__device__ int   g_off  [N_NODES + 1];  // CSR offsets (padded degrees, 4-aligned)
__device__ __align__(16) int g_src [E_PAD];  // row indices; slack = N_NODES sentinel
// Hs buffers have one extra ZERO row at index N_NODES (never written -> stays 0)
__device__ float g_h    [(N_NODES + 1) * HID / 2]; // Hs bf16 buffer A
__device__ float g_x    [(N_NODES + 1) * HID / 2]; // activations bf16 buffer
__device__ float g_y    [(N_NODES + 1) * HID / 2]; // Hs bf16 buffer B
// precomputed hi/lo bf16 weight splits
__device__ __nv_bfloat16 g_W1h[IN_C * HID], g_W1l[IN_C * HID];
__device__ __nv_bfloat16 g_W2h[HID * HID],  g_W2l[HID * HID];
__device__ __nv_bfloat16 g_W3h[HID * HID],  g_W3l[HID * HID];

#define FLAG_AGG  (1ull << 62)
#define FLAG_PREF (2ull << 62)

// ---------------- CSR build --------------------------------------------------
__global__ void count_kernel(const int4* __restrict__ col4) {
    int i = blockIdx.x * 256 + threadIdx.x;
    if (i < E_EDGES / 4) {
        int4 c = col4[i];
        atomicAdd(&g_s.count[c.x], 1);
        atomicAdd(&g_s.count[c.y], 1);
        atomicAdd(&g_s.count[c.z], 1);
        atomicAdd(&g_s.count[c.w], 1);
    }
}

// single-pass exclusive scan over PADDED degrees (decoupled lookback)
// + dinv (real degree) + cursor reset + sentinel fill of slack slots
__global__ void __launch_bounds__(256)
scan_fused_kernel() {
    __shared__ int sh[256];
    __shared__ int s_prefix;
    int b = blockIdx.x, t = threadIdx.x;
    int base = b * 1024 + t * 4;
    int c0 = (base + 0 < N_NODES) ? g_s.count[base + 0] : 0;
    int c1 = (base + 1 < N_NODES) ? g_s.count[base + 1] : 0;
    int c2 = (base + 2 < N_NODES) ? g_s.count[base + 2] : 0;
    int c3 = (base + 3 < N_NODES) ? g_s.count[base + 3] : 0;
    int p0 = (c0 + 3) & ~3, p1 = (c1 + 3) & ~3, p2 = (c2 + 3) & ~3, p3 = (c3 + 3) & ~3;
    int tot = p0 + p1 + p2 + p3;
    sh[t] = tot;
    __syncthreads();
    for (int o = 1; o < 256; o <<= 1) {
        int x = (t >= o) ? sh[t - o] : 0;
        __syncthreads();
        sh[t] += x;
        __syncthreads();
    }
    int btot = sh[255];

    if (t == 0) {
        if (b == 0) {
            s_prefix = 0;
            atomicExch(&g_s.state[0], FLAG_PREF | (unsigned long long)(unsigned)btot);
        } else {
            atomicExch(&g_s.state[b], FLAG_AGG | (unsigned long long)(unsigned)btot);
        }
    }
    if (b > 0 && t < 32) {
        int excl = 0;
        int hi = b - 1;
        for (;;) {
            int idx = hi - 31 + t;
            unsigned long long s;
            unsigned flag;
            for (;;) {
                s = (idx >= 0)
                    ? *((volatile unsigned long long*)&g_s.state[idx])
                    : FLAG_PREF;
                flag = (unsigned)(s >> 62);
                if (__all_sync(0xffffffffu, flag != 0)) break;
            }
            unsigned pm = __ballot_sync(0xffffffffu, flag == 2u);
            int val = (int)(s & 0xffffffffull);
            if (pm) {
                int lp = 31 - __clz(pm);
                int contrib = (t >= lp) ? val : 0;
#pragma unroll
                for (int o = 16; o > 0; o >>= 1)
                    contrib += __shfl_xor_sync(0xffffffffu, contrib, o);
                excl += contrib;
                break;
            } else {
                int contrib = val;
#pragma unroll
                for (int o = 16; o > 0; o >>= 1)
                    contrib += __shfl_xor_sync(0xffffffffu, contrib, o);
                excl += contrib;
                hi -= 32;
            }
        }
        if (t == 0) {
            s_prefix = excl;
            atomicExch(&g_s.state[b],
                       FLAG_PREF | (unsigned long long)(unsigned)(excl + btot));
        }
    }
    __syncthreads();
    int pref = s_prefix;
    int excl = pref + sh[t] - tot;
    int offs[4] = {excl, excl + p0, excl + p0 + p1, excl + p0 + p1 + p2};
    int cs[4] = {c0, c1, c2, c3};
    int ps[4] = {p0, p1, p2, p3};
#pragma unroll
    for (int i = 0; i < 4; i++) {
        int v = base + i;
        if (v < N_NODES) {
            g_off[v] = offs[i];
            g_dinv[v] = rsqrtf((float)cs[i] + 1.0f);
            g_s.count[v] = 0;
            // fill slack slots with sentinel (zero row)
            for (int k = cs[i]; k < ps[i]; k++) g_src[offs[i] + k] = N_NODES;
        }
    }
    if (b == NCHUNK - 1 && t == 255) g_off[N_NODES] = pref + btot;
}

__global__ void scatter_kernel(const int4* __restrict__ row4, const int4* __restrict__ col4) {
    int i = blockIdx.x * 256 + threadIdx.x;
    if (i < E_EDGES / 4) {
        int4 r = row4[i];
        int4 c = col4[i];
        g_src[g_off[c.x] + atomicAdd(&g_s.count[c.x], 1)] = r.x;
        g_src[g_off[c.y] + atomicAdd(&g_s.count[c.y], 1)] = r.y;
        g_src[g_off[c.z] + atomicAdd(&g_s.count[c.z], 1)] = r.z;
        g_src[g_off[c.w] + atomicAdd(&g_s.count[c.w], 1)] = r.w;
    }
}

// ---------------- weight prep: fp32 -> hi/lo bf16 (once, on side stream) ----
__global__ void wprep_kernel(const float* __restrict__ W1,
                             const float* __restrict__ W2,
                             const float* __restrict__ W3) {
    int i = blockIdx.x * 256 + threadIdx.x;
    float w;
    __nv_bfloat16 *ph, *pl;
    int j;
    if (i < IN_C * HID)                { j = i;                      w = W1[j]; ph = g_W1h; pl = g_W1l; }
    else if (i < IN_C * HID + HID*HID) { j = i - IN_C * HID;         w = W2[j]; ph = g_W2h; pl = g_W2l; }
    else if (i < IN_C*HID + 2*HID*HID) { j = i - IN_C*HID - HID*HID; w = W3[j]; ph = g_W3h; pl = g_W3l; }
    else return;
    __nv_bfloat16 h = __float2bfloat16(w);
    ph[j] = h;
    pl[j] = __float2bfloat16(w - __bfloat162float(h));
}

// ---------------- tensor-core MMA helpers -----------------------------------
__device__ __forceinline__ void ldsm_x4(uint32_t& a0, uint32_t& a1, uint32_t& a2,
                                        uint32_t& a3, uint32_t addr) {
    asm volatile("ldmatrix.sync.aligned.m8n8.x4.shared.b16 {%0,%1,%2,%3}, [%4];"
                 : "=r"(a0), "=r"(a1), "=r"(a2), "=r"(a3) : "r"(addr));
}
__device__ __forceinline__ void ldsm_x2t(uint32_t& b0, uint32_t& b1, uint32_t addr) {
    asm volatile("ldmatrix.sync.aligned.m8n8.x2.trans.shared.b16 {%0,%1}, [%2];"
                 : "=r"(b0), "=r"(b1) : "r"(addr));
}
__device__ __forceinline__ void mma_bf16(float* c, uint32_t a0, uint32_t a1,
                                         uint32_t a2, uint32_t a3,
                                         uint32_t b0, uint32_t b1) {
    asm volatile(
        "mma.sync.aligned.m16n8k16.row.col.f32.bf16.bf16.f32 "
        "{%0,%1,%2,%3},{%4,%5,%6,%7},{%8,%9},{%0,%1,%2,%3};"
        : "+f"(c[0]), "+f"(c[1]), "+f"(c[2]), "+f"(c[3])
        : "r"(a0), "r"(a1), "r"(a2), "r"(a3), "r"(b0), "r"(b1));
}

// ---------------- tensor-core GEMM ------------------------------------------
template <int K, bool SCALE, bool F32SRC>
__global__ void __launch_bounds__(128)
gemm_kernel(const void* __restrict__ Xv,
            const __nv_bfloat16* __restrict__ Wh_g,
            const __nv_bfloat16* __restrict__ Wl_g,
            __nv_bfloat162* __restrict__ Hs, int m_base) {
    __shared__ __align__(16) __nv_bfloat16 Xs[64][XP];
    __shared__ __align__(16) __nv_bfloat16 Wh[64][XP];
    __shared__ __align__(16) __nv_bfloat16 Wl[64][XP];

    int tid  = threadIdx.x;
    int wp   = tid >> 5;
    int lane = tid & 31;
    int m0   = m_base + blockIdx.x * 64;

    float c[8][4];
#pragma unroll
    for (int a = 0; a < 8; a++)
#pragma unroll
        for (int b = 0; b < 4; b++) c[a][b] = 0.f;

    uint32_t xs_b = (uint32_t)__cvta_generic_to_shared(&Xs[0][0]);
    uint32_t wh_b = (uint32_t)__cvta_generic_to_shared(&Wh[0][0]);
    uint32_t wl_b = (uint32_t)__cvta_generic_to_shared(&Wl[0][0]);

    for (int kc = 0; kc < K; kc += 64) {
        for (int i = tid; i < 64 * 8; i += 128) {
            int k = i >> 3, q = i & 7;
            *reinterpret_cast<uint4*>(&Wh[k][q * 8]) =
                *reinterpret_cast<const uint4*>(&Wh_g[(kc + k) * HID + q * 8]);
            *reinterpret_cast<uint4*>(&Wl[k][q * 8]) =
                *reinterpret_cast<const uint4*>(&Wl_g[(kc + k) * HID + q * 8]);
        }
        if (F32SRC) {
            const float* X = (const float*)Xv;
#pragma unroll
            for (int l = 0; l < 8; l++) {
                int idx = l * 128 + tid;
                int row = idx >> 4;
                int q   = idx & 15;
                int m   = m0 + row;
                float4 v = make_float4(0.f, 0.f, 0.f, 0.f);
                if (m < N_NODES)
                    v = *reinterpret_cast<const float4*>(&X[(size_t)m * K + kc + q * 4]);
                *reinterpret_cast<__nv_bfloat162*>(&Xs[row][q * 4]) =
                    __float22bfloat162_rn(make_float2(v.x, v.y));
                *reinterpret_cast<__nv_bfloat162*>(&Xs[row][q * 4 + 2]) =
                    __float22bfloat162_rn(make_float2(v.z, v.w));
            }
        } else {
            const __nv_bfloat16* X = (const __nv_bfloat16*)Xv;
#pragma unroll
            for (int l = 0; l < 4; l++) {
                int idx = l * 128 + tid;
                int row = idx >> 3;
                int q   = idx & 7;
                int m   = m0 + row;
                uint4 v = make_uint4(0u, 0u, 0u, 0u);
                if (m < N_NODES)
                    v = *reinterpret_cast<const uint4*>(&X[(size_t)m * K + kc + q * 8]);
                *reinterpret_cast<uint4*>(&Xs[row][q * 8]) = v;
            }
        }
        __syncthreads();

#pragma unroll
        for (int ks = 0; ks < 4; ks++) {
            uint32_t a0, a1, a2, a3;
            int ar = wp * 16 + (lane & 15);
            int ak = ks * 16 + (lane >> 4) * 8;
            ldsm_x4(a0, a1, a2, a3, xs_b + (ar * XP + ak) * 2);
            int kg = ks * 16 + (lane & 15);
#pragma unroll
            for (int nt = 0; nt < 8; nt++) {
                uint32_t b0, b1;
                ldsm_x2t(b0, b1, wh_b + (kg * XP + nt * 8) * 2);
                mma_bf16(c[nt], a0, a1, a2, a3, b0, b1);
                ldsm_x2t(b0, b1, wl_b + (kg * XP + nt * 8) * 2);
                mma_bf16(c[nt], a0, a1, a2, a3, b0, b1);
            }
        }
        __syncthreads();
    }

    int gid = lane >> 2, tig = lane & 3;
    int r0 = m0 + wp * 16 + gid;
    int r1 = r0 + 8;
    if (r0 < N_NODES) {
        float dv = SCALE ? g_dinv[r0] : 1.0f;
#pragma unroll
        for (int nt = 0; nt < 8; nt++)
            Hs[(size_t)r0 * 32 + nt * 4 + tig] =
                __float22bfloat162_rn(make_float2(c[nt][0] * dv, c[nt][1] * dv));
    }
    if (r1 < N_NODES) {
        float dv = SCALE ? g_dinv[r1] : 1.0f;
#pragma unroll
        for (int nt = 0; nt < 8; nt++)
            Hs[(size_t)r1 * 32 + nt * 4 + tig] =
                __float22bfloat162_rn(make_float2(c[nt][2] * dv, c[nt][3] * dv));
    }
}

// multiply bf16 rows by dinv[v] (applied after gemm1, which runs before dinv exists)
__global__ void __launch_bounds__(256)
scale_kernel(__nv_bfloat162* __restrict__ Hs) {
    int idx = blockIdx.x * 256 + threadIdx.x;
    int v = idx >> 5;
    if (v >= N_NODES) return;
    float dv = g_dinv[v];
    float2 f = __bfloat1622float2(Hs[idx]);
    Hs[idx] = __float22bfloat162_rn(make_float2(f.x * dv, f.y * dv));
}

// ------- agg core: padded CSR gather + self-loop + bias + LN + ReLU ---------
// edge segments are 16B-aligned, length % 4 == 0: pure int4 index loads,
// no peel, no scalar tail. Sentinel edges hit the zero row (exact no-op).
__device__ __forceinline__ void agg_node(
    int v, int lane, const __nv_bfloat162* __restrict__ H2,
    const float* __restrict__ bias, const float* __restrict__ lnw,
    const float* __restrict__ lnb, float& y0o, float& y1o) {
    int beg = g_off[v], end = g_off[v + 1];

    float ax = 0.f, ay = 0.f;
    int e = beg;
    for (; e + 8 <= end; e += 8) {
        int4 sa = *reinterpret_cast<const int4*>(&g_src[e]);
        int4 sb = *reinterpret_cast<const int4*>(&g_src[e + 4]);
        float2 h0 = __bfloat1622float2(H2[(size_t)sa.x * 32 + lane]);
        float2 h1 = __bfloat1622float2(H2[(size_t)sa.y * 32 + lane]);
        float2 h2 = __bfloat1622float2(H2[(size_t)sa.z * 32 + lane]);
        float2 h3 = __bfloat1622float2(H2[(size_t)sa.w * 32 + lane]);
        float2 h4 = __bfloat1622float2(H2[(size_t)sb.x * 32 + lane]);
        float2 h5 = __bfloat1622float2(H2[(size_t)sb.y * 32 + lane]);
        float2 h6 = __bfloat1622float2(H2[(size_t)sb.z * 32 + lane]);
        float2 h7 = __bfloat1622float2(H2[(size_t)sb.w * 32 + lane]);
        ax += ((h0.x + h1.x) + (h2.x + h3.x)) + ((h4.x + h5.x) + (h6.x + h7.x));
        ay += ((h0.y + h1.y) + (h2.y + h3.y)) + ((h4.y + h5.y) + (h6.y + h7.y));
    }
    if (e < end) {   // remainder is exactly 4
        int4 sa = *reinterpret_cast<const int4*>(&g_src[e]);
        float2 h0 = __bfloat1622float2(H2[(size_t)sa.x * 32 + lane]);
        float2 h1 = __bfloat1622float2(H2[(size_t)sa.y * 32 + lane]);
        float2 h2 = __bfloat1622float2(H2[(size_t)sa.z * 32 + lane]);
        float2 h3 = __bfloat1622float2(H2[(size_t)sa.w * 32 + lane]);
        ax += (h0.x + h1.x) + (h2.x + h3.x);
        ay += (h0.y + h1.y) + (h2.y + h3.y);
    }

    float dv = g_dinv[v];
    float2 hs = __bfloat1622float2(H2[(size_t)v * 32 + lane]);
    ax = (ax + hs.x) * dv + bias[lane * 2 + 0];
    ay = (ay + hs.y) * dv + bias[lane * 2 + 1];

    float sum = ax + ay;
    float sq  = ax * ax + ay * ay;
#pragma unroll
    for (int o = 16; o > 0; o >>= 1) {
        sum += __shfl_xor_sync(0xffffffffu, sum, o);
        sq  += __shfl_xor_sync(0xffffffffu, sq,  o);
    }
    float mu  = sum * (1.f / 64.f);
    float var = sq * (1.f / 64.f) - mu * mu;
    float r   = rsqrtf(var + 1e-5f);
    float t0 = (ax - mu) * r * lnw[lane * 2 + 0] + lnb[lane * 2 + 0];
    float t1 = (ay - mu) * r * lnw[lane * 2 + 1] + lnb[lane * 2 + 1];
    y0o = fmaxf(t0, 0.f);
    y1o = fmaxf(t1, 0.f);
}

// writes bf16 activations (consumed by tensor-core gemm2/3); node range version
__global__ void __launch_bounds__(256)
agg_ln_kernel(const __nv_bfloat162* __restrict__ H2, const float* __restrict__ bias,
              const float* __restrict__ lnw, const float* __restrict__ lnb,
              __nv_bfloat162* __restrict__ Xo, int v_base, int v_count) {
    int vl = (blockIdx.x * 256 + threadIdx.x) >> 5;
    int lane = threadIdx.x & 31;
    if (vl >= v_count) return;
    int v = v_base + vl;
    float y0, y1;
    agg_node(v, lane, H2, bias, lnw, lnb, y0, y1);
    Xo[(size_t)v * 32 + lane] = __float22bfloat162_rn(make_float2(y0, y1));
}

// layer 3: agg + LN + ReLU + mean-pool + (last block) final linear head
#define POOL_BLOCKS 1184
__global__ void __launch_bounds__(256)
agg_ln_pool_kernel(const __nv_bfloat162* __restrict__ H2, const float* __restrict__ bias,
                   const float* __restrict__ lnw, const float* __restrict__ lnb,
                   const float* __restrict__ Wl, const float* __restrict__ bl,
                   float* __restrict__ out) {
    __shared__ float shp[8 * 64];
    __shared__ int s_last;
    int w    = threadIdx.x >> 5;
    int lane = threadIdx.x & 31;
    int gw   = blockIdx.x * 8 + w;
    const int nw = POOL_BLOCKS * 8;

    float px = 0.f, py = 0.f;
    for (int v = gw; v < N_NODES; v += nw) {
        float y0, y1;
        agg_node(v, lane, H2, bias, lnw, lnb, y0, y1);
        px += y0; py += y1;
    }
    shp[w * 64 + lane * 2 + 0] = px;
    shp[w * 64 + lane * 2 + 1] = py;
    __syncthreads();
    if (threadIdx.x < 64) {
        float s = 0.f;
#pragma unroll
        for (int k = 0; k < 8; k++) s += shp[k * 64 + threadIdx.x];
        atomicAdd(&g_s.pool[threadIdx.x], s);
    }
    __syncthreads();
    if (threadIdx.x == 0) {
        __threadfence();
        unsigned t = atomicAdd(&g_s.done, 1u);
        s_last = (t == POOL_BLOCKS - 1) ? 1 : 0;
    }
    __syncthreads();
    if (s_last) {
        __threadfence();
        int o = threadIdx.x;
        if (o < OUT_F) {
            float s = 0.f;
#pragma unroll
            for (int j = 0; j < HID; j++) s += g_s.pool[j] * Wl[j * OUT_F + o];
            out[o] = s * (1.0f / N_NODES) + bl[o];
        }
    }
}

// ---------------- launch ----------------------------------------------------
extern "C" void kernel_launch(void* const* d_in, const int* in_sizes, int n_in,
                              void* d_out, int out_size) {
    const float* x    = (const float*)d_in[0];
    const int*   ei   = (const int*)  d_in[1];
    const float* W1   = (const float*)d_in[2];
    const float* b1   = (const float*)d_in[3];
    const float* W2   = (const float*)d_in[4];
    const float* b2   = (const float*)d_in[5];
    const float* W3   = (const float*)d_in[6];
    const float* b3   = (const float*)d_in[7];
    const float* ln1w = (const float*)d_in[8];
    const float* ln1b = (const float*)d_in[9];
    const float* ln2w = (const float*)d_in[10];
    const float* ln2b = (const float*)d_in[11];
    const float* ln3w = (const float*)d_in[12];
    const float* ln3b = (const float*)d_in[13];
    const float* Wl   = (const float*)d_in[14];
    const float* bl   = (const float*)d_in[15];
    float* out = (float*)d_out;

    const int4* row4 = (const int4*)(ei);             // edge_index[0]
    const int4* col4 = (const int4*)(ei + E_EDGES);   // edge_index[1]

    __nv_bfloat162* gh = nullptr; cudaGetSymbolAddress((void**)&gh, g_h);
    __nv_bfloat162* gx = nullptr; cudaGetSymbolAddress((void**)&gx, g_x);
    __nv_bfloat162* gy = nullptr; cudaGetSymbolAddress((void**)&gy, g_y);
    void*           gs = nullptr; cudaGetSymbolAddress(&gs, g_s);
    __nv_bfloat16 *w1h = nullptr, *w1l = nullptr, *w2h = nullptr, *w2l = nullptr,
                  *w3h = nullptr, *w3l = nullptr;
    cudaGetSymbolAddress((void**)&w1h, g_W1h);
    cudaGetSymbolAddress((void**)&w1l, g_W1l);
    cudaGetSymbolAddress((void**)&w2h, g_W2h);
    cudaGetSymbolAddress((void**)&w2l, g_W2l);
    cudaGetSymbolAddress((void**)&w3h, g_W3h);
    cudaGetSymbolAddress((void**)&w3l, g_W3l);

    int eB4  = (E_EDGES / 4 + 255) / 256;    // 1563
    int gB   = (N_NODES + 63) / 64;          // 1563 (gemm1: full range)
    int gB0  = HALF0 / 64;                   // 782
    int gB1h = (HALF1 + 63) / 64;            // 781
    int aB   = (N_NODES * 32 + 255) / 256;   // full-range (scale)
    int aB0  = (HALF0 * 32 + 255) / 256;
    int aB1  = (HALF1 * 32 + 255) / 256;

    cudaStream_t s, s2;
    cudaStreamCreateWithFlags(&s,  cudaStreamNonBlocking);
    cudaStreamCreateWithFlags(&s2, cudaStreamNonBlocking);
    cudaEvent_t eFork, eDinv, eScat, eJoin, eM1, eS1, eM2, eS2;
    cudaEventCreateWithFlags(&eFork, cudaEventDisableTiming);
    cudaEventCreateWithFlags(&eDinv, cudaEventDisableTiming);
    cudaEventCreateWithFlags(&eScat, cudaEventDisableTiming);
    cudaEventCreateWithFlags(&eJoin, cudaEventDisableTiming);
    cudaEventCreateWithFlags(&eM1, cudaEventDisableTiming);
    cudaEventCreateWithFlags(&eS1, cudaEventDisableTiming);
    cudaEventCreateWithFlags(&eM2, cudaEventDisableTiming);
    cudaEventCreateWithFlags(&eS2, cudaEventDisableTiming);

    // ---- main stream: CSR build ----
    cudaMemsetAsync(gs, 0, sizeof(Scratch), 0);   // count + scan state + pool + done
    cudaEventRecord(eFork, 0);
    count_kernel<<<eB4, 256>>>(col4);
    scan_fused_kernel<<<NCHUNK, 256>>>();
    cudaEventRecord(eDinv, 0);
    scatter_kernel<<<eB4, 256>>>(row4, col4);
    cudaEventRecord(eScat, 0);

    // ---- side stream: wprep -> gemm1 (no dinv) -> (wait dinv) -> scale ----
    cudaStreamWaitEvent(s, eFork, 0);
    wprep_kernel<<<64, 256, 0, s>>>(W1, W2, W3);
    gemm_kernel<IN_C, false, true><<<gB, 128, 0, s>>>(x, w1h, w1l, gh, 0);
    cudaStreamWaitEvent(s, eDinv, 0);
    scale_kernel<<<aB, 256, 0, s>>>(gh);
    cudaEventRecord(eJoin, s);

    // ---- pipelined layer transitions: half0 on stream 0, half1 on s2 ----
    cudaStreamWaitEvent(0, eJoin, 0);
    cudaStreamWaitEvent(s2, eJoin, 0);
    cudaStreamWaitEvent(s2, eScat, 0);

    // L1 agg(read gh) -> gemm2(write gy) per half
    agg_ln_kernel<<<aB0, 256>>>(gh, b1, ln1w, ln1b, gx, 0, HALF0);
    gemm_kernel<HID, true, false><<<gB0, 128>>>(gx, w2h, w2l, gy, 0);
    cudaEventRecord(eM1, 0);
    agg_ln_kernel<<<aB1, 256, 0, s2>>>(gh, b1, ln1w, ln1b, gx, HALF0, HALF1);
    gemm_kernel<HID, true, false><<<gB1h, 128, 0, s2>>>(gx, w2h, w2l, gy, HALF0);
    cudaEventRecord(eS1, s2);

    cudaStreamWaitEvent(0, eS1, 0);
    cudaStreamWaitEvent(s2, eM1, 0);

    // L2 agg(read gy) -> gemm3(write gh) per half
    agg_ln_kernel<<<aB0, 256>>>(gy, b2, ln2w, ln2b, gx, 0, HALF0);
    gemm_kernel<HID, true, false><<<gB0, 128>>>(gx, w3h, w3l, gh, 0);
    cudaEventRecord(eM2, 0);
    agg_ln_kernel<<<aB1, 256, 0, s2>>>(gy, b2, ln2w, ln2b, gx, HALF0, HALF1);
    gemm_kernel<HID, true, false><<<gB1h, 128, 0, s2>>>(gx, w3h, w3l, gh, HALF0);
    cudaEventRecord(eS2, s2);

    // L3: pool (+ fused final head) needs both halves of gemm3 output (gh)
    cudaStreamWaitEvent(0, eS2, 0);
    cudaStreamWaitEvent(0, eM2, 0);
    agg_ln_pool_kernel<<<POOL_BLOCKS, 256>>>(gh, b3, ln3w, ln3b, Wl, bl, out);

    cudaStreamDestroy(s);
    cudaStreamDestroy(s2);
    cudaEventDestroy(eFork);
    cudaEventDestroy(eDinv);
    cudaEventDestroy(eScat);
    cudaEventDestroy(eJoin);
    cudaEventDestroy(eM1);
    cudaEventDestroy(eS1);
    cudaEventDestroy(eM2);
    cudaEventDestroy(eS2);
}

// round 17
// speedup vs baseline: 1.0627x; 1.0216x over previous
#include <cuda_runtime.h>
#include <cuda_bf16.h>
#include <cstdint>

#define N_NODES 100000
#define E_EDGES 1600000
#define E_PAD   (E_EDGES + 3 * N_NODES + 16)   // CSR padded to 4-multiples per node
#define HID     64
#define IN_C    128
#define OUT_F   25
#define NCHUNK  98   // ceil(N/1024)
#define XP      72   // smem pitch (bf16) -> 144B row stride: conflict-free ldmatrix

// ---------------- device scratch (static: no allocations allowed) ----------
struct Scratch {
    int   count[N_NODES];                 // degree counts, later scatter cursor
    unsigned long long state[NCHUNK];     // decoupled-lookback scan state
    float pool[HID];                      // pooled accumulator
    unsigned int done;                    // pool last-block counter
};
__device__ Scratch g_s;
__device__ float g_dinv [N_NODES];      // rsqrt(deg+1)  (REAL degree)
__device__ int   g_off  [N_NODES + 1];  // CSR offsets (padded degrees, 4-aligned)
__device__ __align__(16) int g_src [E_PAD];  // row indices; slack = N_NODES sentinel
// Hs buffers have one extra ZERO row at index N_NODES (never written -> stays 0)
__device__ float g_h    [(N_NODES + 1) * HID / 2]; // Hs bf16 buffer A
__device__ float g_x    [(N_NODES + 1) * HID / 2]; // activations bf16 buffer
__device__ float g_y    [(N_NODES + 1) * HID / 2]; // Hs bf16 buffer B
// precomputed hi/lo bf16 weight splits
__device__ __nv_bfloat16 g_W1h[IN_C * HID], g_W1l[IN_C * HID];
__device__ __nv_bfloat16 g_W2h[HID * HID],  g_W2l[HID * HID];
__device__ __nv_bfloat16 g_W3h[HID * HID],  g_W3l[HID * HID];

#define FLAG_AGG  (1ull << 62)
#define FLAG_PREF (2ull << 62)

// PDL: wait for programmatic-launch dependency (no-op if launched normally)
__device__ __forceinline__ void gdc_wait() {
    asm volatile("griddepcontrol.wait;" ::: "memory");
}

// ---------------- CSR build --------------------------------------------------
__global__ void count_kernel(const int4* __restrict__ col4) {
    int i = blockIdx.x * 256 + threadIdx.x;
    if (i < E_EDGES / 4) {
        int4 c = col4[i];
        atomicAdd(&g_s.count[c.x], 1);
        atomicAdd(&g_s.count[c.y], 1);
        atomicAdd(&g_s.count[c.z], 1);
        atomicAdd(&g_s.count[c.w], 1);
    }
}

// single-pass exclusive scan over PADDED degrees (decoupled lookback)
// + dinv (real degree) + cursor reset + sentinel fill of slack slots
__global__ void __launch_bounds__(256)
scan_fused_kernel() {
    __shared__ int sh[256];
    __shared__ int s_prefix;
    int b = blockIdx.x, t = threadIdx.x;
    int base = b * 1024 + t * 4;
    int c0 = (base + 0 < N_NODES) ? g_s.count[base + 0] : 0;
    int c1 = (base + 1 < N_NODES) ? g_s.count[base + 1] : 0;
    int c2 = (base + 2 < N_NODES) ? g_s.count[base + 2] : 0;
    int c3 = (base + 3 < N_NODES) ? g_s.count[base + 3] : 0;
    int p0 = (c0 + 3) & ~3, p1 = (c1 + 3) & ~3, p2 = (c2 + 3) & ~3, p3 = (c3 + 3) & ~3;
    int tot = p0 + p1 + p2 + p3;
    sh[t] = tot;
    __syncthreads();
    for (int o = 1; o < 256; o <<= 1) {
        int x = (t >= o) ? sh[t - o] : 0;
        __syncthreads();
        sh[t] += x;
        __syncthreads();
    }
    int btot = sh[255];

    if (t == 0) {
        if (b == 0) {
            s_prefix = 0;
            atomicExch(&g_s.state[0], FLAG_PREF | (unsigned long long)(unsigned)btot);
        } else {
            atomicExch(&g_s.state[b], FLAG_AGG | (unsigned long long)(unsigned)btot);
        }
    }
    if (b > 0 && t < 32) {
        int excl = 0;
        int hi = b - 1;
        for (;;) {
            int idx = hi - 31 + t;
            unsigned long long s;
            unsigned flag;
            for (;;) {
                s = (idx >= 0)
                    ? *((volatile unsigned long long*)&g_s.state[idx])
                    : FLAG_PREF;
                flag = (unsigned)(s >> 62);
                if (__all_sync(0xffffffffu, flag != 0)) break;
            }
            unsigned pm = __ballot_sync(0xffffffffu, flag == 2u);
            int val = (int)(s & 0xffffffffull);
            if (pm) {
                int lp = 31 - __clz(pm);
                int contrib = (t >= lp) ? val : 0;
#pragma unroll
                for (int o = 16; o > 0; o >>= 1)
                    contrib += __shfl_xor_sync(0xffffffffu, contrib, o);
                excl += contrib;
                break;
            } else {
                int contrib = val;
#pragma unroll
                for (int o = 16; o > 0; o >>= 1)
                    contrib += __shfl_xor_sync(0xffffffffu, contrib, o);
                excl += contrib;
                hi -= 32;
            }
        }
        if (t == 0) {
            s_prefix = excl;
            atomicExch(&g_s.state[b],
                       FLAG_PREF | (unsigned long long)(unsigned)(excl + btot));
        }
    }
    __syncthreads();
    int pref = s_prefix;
    int excl = pref + sh[t] - tot;
    int offs[4] = {excl, excl + p0, excl + p0 + p1, excl + p0 + p1 + p2};
    int cs[4] = {c0, c1, c2, c3};
    int ps[4] = {p0, p1, p2, p3};
#pragma unroll
    for (int i = 0; i < 4; i++) {
        int v = base + i;
        if (v < N_NODES) {
            g_off[v] = offs[i];
            g_dinv[v] = rsqrtf((float)cs[i] + 1.0f);
            g_s.count[v] = 0;
            for (int k = cs[i]; k < ps[i]; k++) g_src[offs[i] + k] = N_NODES;
        }
    }
    if (b == NCHUNK - 1 && t == 255) g_off[N_NODES] = pref + btot;
}

__global__ void scatter_kernel(const int4* __restrict__ row4, const int4* __restrict__ col4) {
    int i = blockIdx.x * 256 + threadIdx.x;
    if (i < E_EDGES / 4) {
        int4 r = row4[i];
        int4 c = col4[i];
        g_src[g_off[c.x] + atomicAdd(&g_s.count[c.x], 1)] = r.x;
        g_src[g_off[c.y] + atomicAdd(&g_s.count[c.y], 1)] = r.y;
        g_src[g_off[c.z] + atomicAdd(&g_s.count[c.z], 1)] = r.z;
        g_src[g_off[c.w] + atomicAdd(&g_s.count[c.w], 1)] = r.w;
    }
}

// ---------------- weight prep: fp32 -> hi/lo bf16 (once, on side stream) ----
__global__ void wprep_kernel(const float* __restrict__ W1,
                             const float* __restrict__ W2,
                             const float* __restrict__ W3) {
    int i = blockIdx.x * 256 + threadIdx.x;
    float w;
    __nv_bfloat16 *ph, *pl;
    int j;
    if (i < IN_C * HID)                { j = i;                      w = W1[j]; ph = g_W1h; pl = g_W1l; }
    else if (i < IN_C * HID + HID*HID) { j = i - IN_C * HID;         w = W2[j]; ph = g_W2h; pl = g_W2l; }
    else if (i < IN_C*HID + 2*HID*HID) { j = i - IN_C*HID - HID*HID; w = W3[j]; ph = g_W3h; pl = g_W3l; }
    else return;
    __nv_bfloat16 h = __float2bfloat16(w);
    ph[j] = h;
    pl[j] = __float2bfloat16(w - __bfloat162float(h));
}

// ---------------- tensor-core MMA helpers -----------------------------------
__device__ __forceinline__ void ldsm_x4(uint32_t& a0, uint32_t& a1, uint32_t& a2,
                                        uint32_t& a3, uint32_t addr) {
    asm volatile("ldmatrix.sync.aligned.m8n8.x4.shared.b16 {%0,%1,%2,%3}, [%4];"
                 : "=r"(a0), "=r"(a1), "=r"(a2), "=r"(a3) : "r"(addr));
}
__device__ __forceinline__ void ldsm_x2t(uint32_t& b0, uint32_t& b1, uint32_t addr) {
    asm volatile("ldmatrix.sync.aligned.m8n8.x2.trans.shared.b16 {%0,%1}, [%2];"
                 : "=r"(b0), "=r"(b1) : "r"(addr));
}
__device__ __forceinline__ void mma_bf16(float* c, uint32_t a0, uint32_t a1,
                                         uint32_t a2, uint32_t a3,
                                         uint32_t b0, uint32_t b1) {
    asm volatile(
        "mma.sync.aligned.m16n8k16.row.col.f32.bf16.bf16.f32 "
        "{%0,%1,%2,%3},{%4,%5,%6,%7},{%8,%9},{%0,%1,%2,%3};"
        : "+f"(c[0]), "+f"(c[1]), "+f"(c[2]), "+f"(c[3])
        : "r"(a0), "r"(a1), "r"(a2), "r"(a3), "r"(b0), "r"(b1));
}

// ---------------- tensor-core GEMM ------------------------------------------
// Hs[n] = [dinv[n] *] (X[n] @ W).  PDL variant stages W into smem BEFORE the
// griddepcontrol.wait, overlapping the producer's tail.
template <int K, bool SCALE, bool F32SRC, bool PDL>
__global__ void __launch_bounds__(128)
gemm_kernel(const void* __restrict__ Xv,
            const __nv_bfloat16* __restrict__ Wh_g,
            const __nv_bfloat16* __restrict__ Wl_g,
            __nv_bfloat162* __restrict__ Hs) {
    __shared__ __align__(16) __nv_bfloat16 Xs[64][XP];
    __shared__ __align__(16) __nv_bfloat16 Wh[64][XP];
    __shared__ __align__(16) __nv_bfloat16 Wl[64][XP];

    int tid  = threadIdx.x;
    int wp   = tid >> 5;
    int lane = tid & 31;
    int m0   = blockIdx.x * 64;

    float c[8][4];
#pragma unroll
    for (int a = 0; a < 8; a++)
#pragma unroll
        for (int b = 0; b < 4; b++) c[a][b] = 0.f;

    uint32_t xs_b = (uint32_t)__cvta_generic_to_shared(&Xs[0][0]);
    uint32_t wh_b = (uint32_t)__cvta_generic_to_shared(&Wh[0][0]);
    uint32_t wl_b = (uint32_t)__cvta_generic_to_shared(&Wl[0][0]);

    for (int kc = 0; kc < K; kc += 64) {
        for (int i = tid; i < 64 * 8; i += 128) {
            int k = i >> 3, q = i & 7;
            *reinterpret_cast<uint4*>(&Wh[k][q * 8]) =
                *reinterpret_cast<const uint4*>(&Wh_g[(kc + k) * HID + q * 8]);
            *reinterpret_cast<uint4*>(&Wl[k][q * 8]) =
                *reinterpret_cast<const uint4*>(&Wl_g[(kc + k) * HID + q * 8]);
        }
        if (PDL && kc == 0) gdc_wait();   // X source becomes valid here
        if (F32SRC) {
            const float* X = (const float*)Xv;
#pragma unroll
            for (int l = 0; l < 8; l++) {
                int idx = l * 128 + tid;
                int row = idx >> 4;
                int q   = idx & 15;
                int m   = m0 + row;
                float4 v = make_float4(0.f, 0.f, 0.f, 0.f);
                if (m < N_NODES)
                    v = *reinterpret_cast<const float4*>(&X[(size_t)m * K + kc + q * 4]);
                *reinterpret_cast<__nv_bfloat162*>(&Xs[row][q * 4]) =
                    __float22bfloat162_rn(make_float2(v.x, v.y));
                *reinterpret_cast<__nv_bfloat162*>(&Xs[row][q * 4 + 2]) =
                    __float22bfloat162_rn(make_float2(v.z, v.w));
            }
        } else {
            const __nv_bfloat16* X = (const __nv_bfloat16*)Xv;
#pragma unroll
            for (int l = 0; l < 4; l++) {
                int idx = l * 128 + tid;
                int row = idx >> 3;
                int q   = idx & 7;
                int m   = m0 + row;
                uint4 v = make_uint4(0u, 0u, 0u, 0u);
                if (m < N_NODES)
                    v = *reinterpret_cast<const uint4*>(&X[(size_t)m * K + kc + q * 8]);
                *reinterpret_cast<uint4*>(&Xs[row][q * 8]) = v;
            }
        }
        __syncthreads();

#pragma unroll
        for (int ks = 0; ks < 4; ks++) {
            uint32_t a0, a1, a2, a3;
            int ar = wp * 16 + (lane & 15);
            int ak = ks * 16 + (lane >> 4) * 8;
            ldsm_x4(a0, a1, a2, a3, xs_b + (ar * XP + ak) * 2);
            int kg = ks * 16 + (lane & 15);
#pragma unroll
            for (int nt = 0; nt < 8; nt++) {
                uint32_t b0, b1;
                ldsm_x2t(b0, b1, wh_b + (kg * XP + nt * 8) * 2);
                mma_bf16(c[nt], a0, a1, a2, a3, b0, b1);
                ldsm_x2t(b0, b1, wl_b + (kg * XP + nt * 8) * 2);
                mma_bf16(c[nt], a0, a1, a2, a3, b0, b1);
            }
        }
        __syncthreads();
    }

    int gid = lane >> 2, tig = lane & 3;
    int r0 = m0 + wp * 16 + gid;
    int r1 = r0 + 8;
    if (r0 < N_NODES) {
        float dv = SCALE ? g_dinv[r0] : 1.0f;
#pragma unroll
        for (int nt = 0; nt < 8; nt++)
            Hs[(size_t)r0 * 32 + nt * 4 + tig] =
                __float22bfloat162_rn(make_float2(c[nt][0] * dv, c[nt][1] * dv));
    }
    if (r1 < N_NODES) {
        float dv = SCALE ? g_dinv[r1] : 1.0f;
#pragma unroll
        for (int nt = 0; nt < 8; nt++)
            Hs[(size_t)r1 * 32 + nt * 4 + tig] =
                __float22bfloat162_rn(make_float2(c[nt][2] * dv, c[nt][3] * dv));
    }
}

// multiply bf16 rows by dinv[v] (applied after gemm1, which runs before dinv exists)
__global__ void __launch_bounds__(256)
scale_kernel(__nv_bfloat162* __restrict__ Hs) {
    int idx = blockIdx.x * 256 + threadIdx.x;
    int v = idx >> 5;
    if (v >= N_NODES) return;
    float dv = g_dinv[v];
    float2 f = __bfloat1622float2(Hs[idx]);
    Hs[idx] = __float22bfloat162_rn(make_float2(f.x * dv, f.y * dv));
}

// ------- agg core: padded CSR gather + self-loop + bias + LN + ReLU ---------
__device__ __forceinline__ void agg_node(
    int v, int lane, const __nv_bfloat162* __restrict__ H2,
    const float* __restrict__ bias, const float* __restrict__ lnw,
    const float* __restrict__ lnb, float& y0o, float& y1o) {
    int beg = g_off[v], end = g_off[v + 1];

    float ax = 0.f, ay = 0.f;
    int e = beg;
    for (; e + 8 <= end; e += 8) {
        int4 sa = *reinterpret_cast<const int4*>(&g_src[e]);
        int4 sb = *reinterpret_cast<const int4*>(&g_src[e + 4]);
        float2 h0 = __bfloat1622float2(H2[(size_t)sa.x * 32 + lane]);
        float2 h1 = __bfloat1622float2(H2[(size_t)sa.y * 32 + lane]);
        float2 h2 = __bfloat1622float2(H2[(size_t)sa.z * 32 + lane]);
        float2 h3 = __bfloat1622float2(H2[(size_t)sa.w * 32 + lane]);
        float2 h4 = __bfloat1622float2(H2[(size_t)sb.x * 32 + lane]);
        float2 h5 = __bfloat1622float2(H2[(size_t)sb.y * 32 + lane]);
        float2 h6 = __bfloat1622float2(H2[(size_t)sb.z * 32 + lane]);
        float2 h7 = __bfloat1622float2(H2[(size_t)sb.w * 32 + lane]);
        ax += ((h0.x + h1.x) + (h2.x + h3.x)) + ((h4.x + h5.x) + (h6.x + h7.x));
        ay += ((h0.y + h1.y) + (h2.y + h3.y)) + ((h4.y + h5.y) + (h6.y + h7.y));
    }
    if (e < end) {   // remainder is exactly 4
        int4 sa = *reinterpret_cast<const int4*>(&g_src[e]);
        float2 h0 = __bfloat1622float2(H2[(size_t)sa.x * 32 + lane]);
        float2 h1 = __bfloat1622float2(H2[(size_t)sa.y * 32 + lane]);
        float2 h2 = __bfloat1622float2(H2[(size_t)sa.z * 32 + lane]);
        float2 h3 = __bfloat1622float2(H2[(size_t)sa.w * 32 + lane]);
        ax += (h0.x + h1.x) + (h2.x + h3.x);
        ay += (h0.y + h1.y) + (h2.y + h3.y);
    }

    float dv = g_dinv[v];
    float2 hs = __bfloat1622float2(H2[(size_t)v * 32 + lane]);
    ax = (ax + hs.x) * dv + bias[lane * 2 + 0];
    ay = (ay + hs.y) * dv + bias[lane * 2 + 1];

    float sum = ax + ay;
    float sq  = ax * ax + ay * ay;
#pragma unroll
    for (int o = 16; o > 0; o >>= 1) {
        sum += __shfl_xor_sync(0xffffffffu, sum, o);
        sq  += __shfl_xor_sync(0xffffffffu, sq,  o);
    }
    float mu  = sum * (1.f / 64.f);
    float var = sq * (1.f / 64.f) - mu * mu;
    float r   = rsqrtf(var + 1e-5f);
    float t0 = (ax - mu) * r * lnw[lane * 2 + 0] + lnb[lane * 2 + 0];
    float t1 = (ay - mu) * r * lnw[lane * 2 + 1] + lnb[lane * 2 + 1];
    y0o = fmaxf(t0, 0.f);
    y1o = fmaxf(t1, 0.f);
}

// writes bf16 activations (consumed by tensor-core gemm2/3)
template <bool PDL>
__global__ void __launch_bounds__(256)
agg_ln_kernel(const __nv_bfloat162* __restrict__ H2, const float* __restrict__ bias,
              const float* __restrict__ lnw, const float* __restrict__ lnb,
              __nv_bfloat162* __restrict__ Xo) {
    if (PDL) gdc_wait();
    int v = (blockIdx.x * 256 + threadIdx.x) >> 5;
    int lane = threadIdx.x & 31;
    if (v >= N_NODES) return;
    float y0, y1;
    agg_node(v, lane, H2, bias, lnw, lnb, y0, y1);
    Xo[(size_t)v * 32 + lane] = __float22bfloat162_rn(make_float2(y0, y1));
}

// layer 3: agg + LN + ReLU + mean-pool + (last block) final linear head
#define POOL_BLOCKS 1184
__global__ void __launch_bounds__(256)
agg_ln_pool_kernel(const __nv_bfloat162* __restrict__ H2, const float* __restrict__ bias,
                   const float* __restrict__ lnw, const float* __restrict__ lnb,
                   const float* __restrict__ Wl, const float* __restrict__ bl,
                   float* __restrict__ out) {
    gdc_wait();
    __shared__ float shp[8 * 64];
    __shared__ int s_last;
    int w    = threadIdx.x >> 5;
    int lane = threadIdx.x & 31;
    int gw   = blockIdx.x * 8 + w;
    const int nw = POOL_BLOCKS * 8;

    float px = 0.f, py = 0.f;
    for (int v = gw; v < N_NODES; v += nw) {
        float y0, y1;
        agg_node(v, lane, H2, bias, lnw, lnb, y0, y1);
        px += y0; py += y1;
    }
    shp[w * 64 + lane * 2 + 0] = px;
    shp[w * 64 + lane * 2 + 1] = py;
    __syncthreads();
    if (threadIdx.x < 64) {
        float s = 0.f;
#pragma unroll
        for (int k = 0; k < 8; k++) s += shp[k * 64 + threadIdx.x];
        atomicAdd(&g_s.pool[threadIdx.x], s);
    }
    __syncthreads();
    if (threadIdx.x == 0) {
        __threadfence();
        unsigned t = atomicAdd(&g_s.done, 1u);
        s_last = (t == POOL_BLOCKS - 1) ? 1 : 0;
    }
    __syncthreads();
    if (s_last) {
        __threadfence();
        int o = threadIdx.x;
        if (o < OUT_F) {
            float s = 0.f;
#pragma unroll
            for (int j = 0; j < HID; j++) s += g_s.pool[j] * Wl[j * OUT_F + o];
            out[o] = s * (1.0f / N_NODES) + bl[o];
        }
    }
}

// ---------------- launch ----------------------------------------------------
template <typename KF, typename... Args>
static void launch_pdl(KF kf, int grid, int block, Args... args) {
    cudaLaunchConfig_t cfg = {};
    cfg.gridDim  = dim3((unsigned)grid, 1, 1);
    cfg.blockDim = dim3((unsigned)block, 1, 1);
    cfg.dynamicSmemBytes = 0;
    cfg.stream = 0;
    cudaLaunchAttribute at;
    at.id = cudaLaunchAttributeProgrammaticStreamSerialization;
    at.val.programmaticStreamSerializationAllowed = 1;
    cfg.attrs = &at;
    cfg.numAttrs = 1;
    cudaLaunchKernelEx(&cfg, kf, args...);
}

extern "C" void kernel_launch(void* const* d_in, const int* in_sizes, int n_in,
                              void* d_out, int out_size) {
    const float* x    = (const float*)d_in[0];
    const int*   ei   = (const int*)  d_in[1];
    const float* W1   = (const float*)d_in[2];
    const float* b1   = (const float*)d_in[3];
    const float* W2   = (const float*)d_in[4];
    const float* b2   = (const float*)d_in[5];
    const float* W3   = (const float*)d_in[6];
    const float* b3   = (const float*)d_in[7];
    const float* ln1w = (const float*)d_in[8];
    const float* ln1b = (const float*)d_in[9];
    const float* ln2w = (const float*)d_in[10];
    const float* ln2b = (const float*)d_in[11];
    const float* ln3w = (const float*)d_in[12];
    const float* ln3b = (const float*)d_in[13];
    const float* Wl   = (const float*)d_in[14];
    const float* bl   = (const float*)d_in[15];
    float* out = (float*)d_out;

    const int4* row4 = (const int4*)(ei);             // edge_index[0]
    const int4* col4 = (const int4*)(ei + E_EDGES);   // edge_index[1]

    __nv_bfloat162* gh = nullptr; cudaGetSymbolAddress((void**)&gh, g_h);
    __nv_bfloat162* gx = nullptr; cudaGetSymbolAddress((void**)&gx, g_x);
    __nv_bfloat162* gy = nullptr; cudaGetSymbolAddress((void**)&gy, g_y);
    void*           gs = nullptr; cudaGetSymbolAddress(&gs, g_s);
    __nv_bfloat16 *w1h = nullptr, *w1l = nullptr, *w2h = nullptr, *w2l = nullptr,
                  *w3h = nullptr, *w3l = nullptr;
    cudaGetSymbolAddress((void**)&w1h, g_W1h);
    cudaGetSymbolAddress((void**)&w1l, g_W1l);
    cudaGetSymbolAddress((void**)&w2h, g_W2h);
    cudaGetSymbolAddress((void**)&w2l, g_W2l);
    cudaGetSymbolAddress((void**)&w3h, g_W3h);
    cudaGetSymbolAddress((void**)&w3l, g_W3l);

    int eB4 = (E_EDGES / 4 + 255) / 256;    // 1563
    int gB  = (N_NODES + 63) / 64;          // 1563
    int aB  = (N_NODES * 32 + 255) / 256;   // 12500

    cudaStream_t s;
    cudaStreamCreateWithFlags(&s, cudaStreamNonBlocking);
    cudaEvent_t eFork, eDinv, eJoin;
    cudaEventCreateWithFlags(&eFork, cudaEventDisableTiming);
    cudaEventCreateWithFlags(&eDinv, cudaEventDisableTiming);
    cudaEventCreateWithFlags(&eJoin, cudaEventDisableTiming);

    // ---- main stream: CSR build ----
    cudaMemsetAsync(gs, 0, sizeof(Scratch), 0);   // count + scan state + pool + done
    cudaEventRecord(eFork, 0);
    count_kernel<<<eB4, 256>>>(col4);
    scan_fused_kernel<<<NCHUNK, 256>>>();
    cudaEventRecord(eDinv, 0);
    scatter_kernel<<<eB4, 256>>>(row4, col4);

    // ---- side stream: wprep -> gemm1 (no dinv) -> (wait dinv) -> scale ----
    cudaStreamWaitEvent(s, eFork, 0);
    wprep_kernel<<<64, 256, 0, s>>>(W1, W2, W3);
    gemm_kernel<IN_C, false, true, false><<<gB, 128, 0, s>>>(x, w1h, w1l, gh);
    cudaStreamWaitEvent(s, eDinv, 0);
    scale_kernel<<<aB, 256, 0, s>>>(gh);
    cudaEventRecord(eJoin, s);
    cudaStreamWaitEvent(0, eJoin, 0);

    // ---- PDL chain on stream 0: agg1 -> gemm2 -> agg2 -> gemm3 -> pool ----
    agg_ln_kernel<false><<<aB, 256>>>(gh, b1, ln1w, ln1b, gx);
    launch_pdl(gemm_kernel<HID, true, false, true>, gB, 128,
               (const void*)gx, (const __nv_bfloat16*)w2h,
               (const __nv_bfloat16*)w2l, gy);
    launch_pdl(agg_ln_kernel<true>, aB, 256,
               (const __nv_bfloat162*)gy, b2, ln2w, ln2b, gx);
    launch_pdl(gemm_kernel<HID, true, false, true>, gB, 128,
               (const void*)gx, (const __nv_bfloat16*)w3h,
               (const __nv_bfloat16*)w3l, gh);
    launch_pdl(agg_ln_pool_kernel, POOL_BLOCKS, 256,
               (const __nv_bfloat162*)gh, b3, ln3w, ln3b, Wl, bl, out);

    cudaStreamDestroy(s);
    cudaEventDestroy(eFork);
    cudaEventDestroy(eDinv);
    cudaEventDestroy(eJoin);
}